// round 1
// baseline (speedup 1.0000x reference)
#include <cuda_runtime.h>
#include <math.h>

// Problem dims (fixed by the dataset)
#define N_TOK (8 * 4096)   // 32768 tokens
#define F_IN  512
#define F_HID 2048
#define F_OUT 512

// ---------------- scratch (static device globals; no runtime alloc) ----------
__device__ float g_lo1[F_IN],  g_cp1[F_IN],  g_den1[F_IN];
__device__ float g_lo2[F_HID], g_cp2[F_HID], g_den2[F_HID];
__device__ float g_invM1[F_IN * F_IN];           //   1 MB
__device__ float g_invM2[F_HID * F_HID];         //  16 MB
__device__ float g_W1pT[F_IN * F_HID];           // [512][2048]  (W1 @ invM1)^T
__device__ float g_W2pT[F_HID * F_OUT];          // [2048][512]  (W2 @ invM2)^T
__device__ float g_h[(size_t)N_TOK * F_HID];     // 256 MB intermediate

// ---------------------------------------------------------------------------
// Thomas factorization prep: parallel elementwise transforms, then a single-
// thread scan computing den_i = diag_i - lo_i*cp_{i-1}, cp_i = up_i/den_i.
// On exit: lo[i]=tanh(l[i-1]), den[i]=denominators, cp[i]=modified upper.
// ---------------------------------------------------------------------------
__global__ void prep_tridiag(const float* __restrict__ d,
                             const float* __restrict__ l,
                             const float* __restrict__ u,
                             int n, float* lo, float* cp, float* den) {
    int t = threadIdx.x;
    for (int i = t; i < n; i += blockDim.x) {
        float di = d[i];
        float sp = (di > 20.f) ? di : log1pf(expf(di));   // softplus
        den[i] = sp + 2.f;                                 // diag (pre-scan)
        lo[i]  = (i > 0)     ? tanhf(l[i - 1]) : 0.f;
        cp[i]  = (i < n - 1) ? tanhf(u[i])     : 0.f;      // up (pre-scan)
    }
    __syncthreads();
    if (t == 0) {
        float prev_cp = 0.f;
        for (int i = 0; i < n; i++) {
            float deni = den[i] - lo[i] * prev_cp;
            den[i] = deni;
            prev_cp = cp[i] / deni;
            cp[i] = prev_cp;
        }
    }
}

// ---------------------------------------------------------------------------
// Explicit tridiagonal inverse: column j = Thomas solve of M z = e_j.
// One thread per column; writes are coalesced across adjacent columns.
// ---------------------------------------------------------------------------
__global__ void inv_cols(const float* __restrict__ lo,
                         const float* __restrict__ cp,
                         const float* __restrict__ den,
                         int n, float* __restrict__ inv) {
    int j = blockIdx.x * blockDim.x + threadIdx.x;
    if (j >= n) return;
    // forward elimination with RHS = e_j
    for (int i = 0; i < j; i++) inv[(size_t)i * n + j] = 0.f;
    float prev = 1.f / den[j];
    inv[(size_t)j * n + j] = prev;
    for (int i = j + 1; i < n; i++) {
        prev = (-lo[i] * prev) / den[i];
        inv[(size_t)i * n + j] = prev;
    }
    // back substitution: z_i = d'_i - cp_i * z_{i+1}
    float nxt = prev;                 // row n-1 value already stored
    for (int i = n - 2; i >= 0; i--) {
        float zi = inv[(size_t)i * n + j] - cp[i] * nxt;
        inv[(size_t)i * n + j] = zi;
        nxt = zi;
    }
}

// ---------------------------------------------------------------------------
// Tiled fp32 GEMM: C[M,N] = A[M,K] @ B[K,N] (+bias[N]) (+relu)
// BM=BN=128, BK=8, 256 threads, 8x8 microtile. Requires M,N %128==0, K %8==0.
// TRANS_OUT: write C^T (C treated as [N][M]).
// ---------------------------------------------------------------------------
template <bool RELU, bool TRANS_OUT>
__global__ void __launch_bounds__(256) sgemm(
    int M, int N, int K,
    const float* __restrict__ A,
    const float* __restrict__ B,
    const float* __restrict__ bias,
    float* __restrict__ C) {
    constexpr int BM = 128, BN = 128, BK = 8;
    __shared__ float As[BK][BM];   // A tile, transposed
    __shared__ float Bs[BK][BN];

    const int tid  = threadIdx.x;
    const int brow = blockIdx.y;   // M tile
    const int bcol = blockIdx.x;   // N tile

    const float* Ab = A + (size_t)brow * BM * K;
    const float* Bb = B + (size_t)bcol * BN;

    const int aRow = tid >> 1;             // 0..127
    const int aCol = (tid & 1) * 4;        // 0 or 4
    const int bRow = tid >> 5;             // 0..7
    const int bCol = (tid & 31) * 4;       // 0..124

    const int tRow = (tid >> 4) * 8;       // 0..120
    const int tCol = (tid & 15) * 8;       // 0..120

    float acc[8][8] = {};

    for (int k0 = 0; k0 < K; k0 += BK) {
        float4 a4 = *reinterpret_cast<const float4*>(Ab + (size_t)aRow * K + k0 + aCol);
        As[aCol + 0][aRow] = a4.x;
        As[aCol + 1][aRow] = a4.y;
        As[aCol + 2][aRow] = a4.z;
        As[aCol + 3][aRow] = a4.w;
        *reinterpret_cast<float4*>(&Bs[bRow][bCol]) =
            *reinterpret_cast<const float4*>(Bb + (size_t)(k0 + bRow) * N + bCol);
        __syncthreads();

#pragma unroll
        for (int k = 0; k < BK; k++) {
            float4 a0 = *reinterpret_cast<const float4*>(&As[k][tRow]);
            float4 a1 = *reinterpret_cast<const float4*>(&As[k][tRow + 4]);
            float4 b0 = *reinterpret_cast<const float4*>(&Bs[k][tCol]);
            float4 b1 = *reinterpret_cast<const float4*>(&Bs[k][tCol + 4]);
            float ar[8] = {a0.x, a0.y, a0.z, a0.w, a1.x, a1.y, a1.z, a1.w};
            float br[8] = {b0.x, b0.y, b0.z, b0.w, b1.x, b1.y, b1.z, b1.w};
#pragma unroll
            for (int i = 0; i < 8; i++)
#pragma unroll
                for (int j = 0; j < 8; j++)
                    acc[i][j] = fmaf(ar[i], br[j], acc[i][j]);
        }
        __syncthreads();
    }

    const int rowBase = brow * BM + tRow;
    const int colBase = bcol * BN + tCol;

    float bj[8];
#pragma unroll
    for (int j = 0; j < 8; j++) bj[j] = bias ? bias[colBase + j] : 0.f;

    if (TRANS_OUT) {
#pragma unroll
        for (int i = 0; i < 8; i++)
#pragma unroll
            for (int j = 0; j < 8; j++) {
                float v = acc[i][j] + bj[j];
                if (RELU) v = fmaxf(v, 0.f);
                C[(size_t)(colBase + j) * M + rowBase + i] = v;
            }
    } else {
#pragma unroll
        for (int i = 0; i < 8; i++) {
            float4 o0, o1;
            float v;
            v = acc[i][0] + bj[0]; o0.x = RELU ? fmaxf(v, 0.f) : v;
            v = acc[i][1] + bj[1]; o0.y = RELU ? fmaxf(v, 0.f) : v;
            v = acc[i][2] + bj[2]; o0.z = RELU ? fmaxf(v, 0.f) : v;
            v = acc[i][3] + bj[3]; o0.w = RELU ? fmaxf(v, 0.f) : v;
            v = acc[i][4] + bj[4]; o1.x = RELU ? fmaxf(v, 0.f) : v;
            v = acc[i][5] + bj[5]; o1.y = RELU ? fmaxf(v, 0.f) : v;
            v = acc[i][6] + bj[6]; o1.z = RELU ? fmaxf(v, 0.f) : v;
            v = acc[i][7] + bj[7]; o1.w = RELU ? fmaxf(v, 0.f) : v;
            float* cp0 = C + (size_t)(rowBase + i) * N + colBase;
            *reinterpret_cast<float4*>(cp0)     = o0;
            *reinterpret_cast<float4*>(cp0 + 4) = o1;
        }
    }
}

// ---------------------------------------------------------------------------
extern "C" void kernel_launch(void* const* d_in, const int* in_sizes, int n_in,
                              void* d_out, int out_size) {
    const float* x  = (const float*)d_in[0];
    const float* d1 = (const float*)d_in[1];
    const float* l1 = (const float*)d_in[2];
    const float* u1 = (const float*)d_in[3];
    const float* W1 = (const float*)d_in[4];
    const float* b1 = (const float*)d_in[5];
    const float* d2 = (const float*)d_in[6];
    const float* l2 = (const float*)d_in[7];
    const float* u2 = (const float*)d_in[8];
    const float* W2 = (const float*)d_in[9];
    const float* b2 = (const float*)d_in[10];
    float* out = (float*)d_out;

    float *lo1, *cp1, *den1, *lo2, *cp2, *den2;
    float *invM1, *invM2, *W1pT, *W2pT, *h;
    cudaGetSymbolAddress((void**)&lo1,  g_lo1);
    cudaGetSymbolAddress((void**)&cp1,  g_cp1);
    cudaGetSymbolAddress((void**)&den1, g_den1);
    cudaGetSymbolAddress((void**)&lo2,  g_lo2);
    cudaGetSymbolAddress((void**)&cp2,  g_cp2);
    cudaGetSymbolAddress((void**)&den2, g_den2);
    cudaGetSymbolAddress((void**)&invM1, g_invM1);
    cudaGetSymbolAddress((void**)&invM2, g_invM2);
    cudaGetSymbolAddress((void**)&W1pT, g_W1pT);
    cudaGetSymbolAddress((void**)&W2pT, g_W2pT);
    cudaGetSymbolAddress((void**)&h,    g_h);

    // 1) Thomas factorizations (shared across all tokens)
    prep_tridiag<<<1, 256>>>(d1, l1, u1, F_IN,  lo1, cp1, den1);
    prep_tridiag<<<1, 256>>>(d2, l2, u2, F_HID, lo2, cp2, den2);

    // 2) Explicit inverses (one Thomas solve per column)
    inv_cols<<<F_IN  / 128, 128>>>(lo1, cp1, den1, F_IN,  invM1);
    inv_cols<<<F_HID / 128, 128>>>(lo2, cp2, den2, F_HID, invM2);

    // 3) Fold tridiagonal solves into weights (write transposed):
    //    W1pT[f][o] = (W1 @ invM1)[o][f]   -> [512][2048]
    //    W2pT[f][o] = (W2 @ invM2)[o][f]   -> [2048][512]
    sgemm<false, true><<<dim3(F_IN / 128,  F_HID / 128), 256>>>(
        F_HID, F_IN, F_IN, W1, invM1, nullptr, W1pT);
    sgemm<false, true><<<dim3(F_HID / 128, F_OUT / 128), 256>>>(
        F_OUT, F_HID, F_HID, W2, invM2, nullptr, W2pT);

    // 4) h = relu(x @ W1pT + b1)   [32768, 2048]
    sgemm<true, false><<<dim3(F_HID / 128, N_TOK / 128), 256>>>(
        N_TOK, F_HID, F_IN, x, W1pT, b1, h);

    // 5) out = h @ W2pT + b2       [32768, 512]
    sgemm<false, false><<<dim3(F_OUT / 128, N_TOK / 128), 256>>>(
        N_TOK, F_OUT, F_HID, h, W2pT, b2, out);
}

// round 3
// speedup vs baseline: 1.9141x; 1.9141x over previous
#include <cuda_runtime.h>
#include <cuda_bf16.h>
#include <math.h>
#include <stdint.h>

#define N_TOK 32768
#define F_IN  512
#define F_HID 2048
#define F_OUT 512

// ---------------- scratch (static device globals; no runtime alloc) ----------
__device__ float g_lo1[F_IN],  g_cp1[F_IN],  g_rd1[F_IN];
__device__ float g_lo2[F_HID], g_cp2[F_HID], g_rd2[F_HID];
__device__ float g_Y1[F_IN * F_HID];                 // solve(M1^T, W1^T): [512][2048]
__device__ float g_Y2[F_HID * F_OUT];                // [2048][512]
__device__ __nv_bfloat16 g_W1h[F_HID * F_IN];        // B1 hi  [2048][512]
__device__ __nv_bfloat16 g_W1l[F_HID * F_IN];        // B1 lo
__device__ __nv_bfloat16 g_W2h[F_OUT * F_HID];       // B2 hi  [512][2048]
__device__ __nv_bfloat16 g_W2l[F_OUT * F_HID];       // B2 lo
__device__ __nv_bfloat16 g_xh[(size_t)N_TOK * F_IN]; // x hi   32 MB
__device__ __nv_bfloat16 g_xl[(size_t)N_TOK * F_IN]; // x lo
__device__ __nv_bfloat16 g_hh[(size_t)N_TOK * F_HID]; // h hi  128 MB
__device__ __nv_bfloat16 g_hl[(size_t)N_TOK * F_HID]; // h lo  128 MB

// ======================= small helpers =======================
__device__ __forceinline__ uint32_t smem_u32(const void* p) {
    uint32_t a;
    asm("{ .reg .u64 t; cvta.to.shared.u64 t, %1; cvt.u32.u64 %0, t; }"
        : "=r"(a) : "l"(p));
    return a;
}

__device__ __forceinline__ void cp16(uint32_t dst, const void* src) {
    asm volatile("cp.async.cg.shared.global [%0], [%1], 16;" :: "r"(dst), "l"(src));
}
__device__ __forceinline__ void cp_commit() {
    asm volatile("cp.async.commit_group;" ::: "memory");
}
template <int NN> __device__ __forceinline__ void cp_wait() {
    asm volatile("cp.async.wait_group %0;" :: "n"(NN) : "memory");
}

__device__ __forceinline__ void ldm_x4(uint32_t& r0, uint32_t& r1, uint32_t& r2,
                                       uint32_t& r3, uint32_t a) {
    asm volatile("ldmatrix.sync.aligned.m8n8.x4.shared.b16 {%0,%1,%2,%3}, [%4];"
        : "=r"(r0), "=r"(r1), "=r"(r2), "=r"(r3) : "r"(a));
}

__device__ __forceinline__ void mma16816(float* c, const uint32_t* a,
                                         uint32_t b0, uint32_t b1) {
    asm volatile("mma.sync.aligned.m16n8k16.row.col.f32.bf16.bf16.f32 "
        "{%0,%1,%2,%3}, {%4,%5,%6,%7}, {%8,%9}, {%0,%1,%2,%3};"
        : "+f"(c[0]), "+f"(c[1]), "+f"(c[2]), "+f"(c[3])
        : "r"(a[0]), "r"(a[1]), "r"(a[2]), "r"(a[3]), "r"(b0), "r"(b1));
}

// split fp32 pair -> packed bf16 hi pair + bf16 lo pair (round-to-nearest split)
__device__ __forceinline__ void split2(float a, float b, uint32_t& hi, uint32_t& lo) {
    __nv_bfloat16 ha = __float2bfloat16(a), hb = __float2bfloat16(b);
    float ra = a - __bfloat162float(ha);
    float rb = b - __bfloat162float(hb);
    __nv_bfloat16 la = __float2bfloat16(ra), lb = __float2bfloat16(rb);
    hi = ((uint32_t)__bfloat16_as_ushort(hb) << 16) | (uint32_t)__bfloat16_as_ushort(ha);
    lo = ((uint32_t)__bfloat16_as_ushort(lb) << 16) | (uint32_t)__bfloat16_as_ushort(la);
}

// ======================= prep kernels =======================
// Thomas factorization of M^T (block 0: layer 1, block 1: layer 2).
// M^T: sub-diag = tanh(u[i-1]), super-diag = tanh(l[i]).
__global__ void prep_both(const float* d1, const float* l1, const float* u1,
                          const float* d2, const float* l2, const float* u2,
                          float* lo1, float* cp1, float* rd1,
                          float* lo2, float* cp2, float* rd2) {
    __shared__ float sd[2048], slo[2048], sup[2048];
    const float *d, *l, *u; float *lo, *cp, *rd; int n;
    if (blockIdx.x == 0) { d = d1; l = l1; u = u1; lo = lo1; cp = cp1; rd = rd1; n = F_IN; }
    else                 { d = d2; l = l2; u = u2; lo = lo2; cp = cp2; rd = rd2; n = F_HID; }
    int t = threadIdx.x;
    for (int i = t; i < n; i += blockDim.x) {
        float di = d[i];
        float sp = (di > 20.f) ? di : log1pf(expf(di));
        sd[i]  = sp + 2.f;
        slo[i] = (i > 0)     ? tanhf(u[i - 1]) : 0.f;
        sup[i] = (i < n - 1) ? tanhf(l[i])     : 0.f;
    }
    __syncthreads();
    if (t == 0) {
        float cprev = 0.f;
        for (int i = 0; i < n; i++) {
            float den = sd[i] - slo[i] * cprev;
            float r = 1.f / den;
            sd[i] = r;
            cprev = sup[i] * r;
            sup[i] = cprev;
        }
    }
    __syncthreads();
    for (int i = t; i < n; i += blockDim.x) {
        rd[i] = sd[i]; cp[i] = sup[i]; lo[i] = slo[i];
    }
}

// Solve M^T Y = R^T. R: [nrhs][n] row-major; Y: [n][nrhs]. 1 thread / RHS.
__global__ void solve_rhs(const float* __restrict__ lo, const float* __restrict__ cp,
                          const float* __restrict__ rd, const float* __restrict__ R,
                          int n, int nrhs, float* __restrict__ Y) {
    int j = blockIdx.x * blockDim.x + threadIdx.x;
    if (j >= nrhs) return;
    const float* r = R + (size_t)j * n;
    float z = r[0] * rd[0];
    Y[j] = z;
    for (int i = 1; i < n; i++) {
        z = (r[i] - lo[i] * z) * rd[i];
        Y[(size_t)i * nrhs + j] = z;
    }
    float y = z;
    for (int i = n - 2; i >= 0; i--) {
        y = Y[(size_t)i * nrhs + j] - cp[i] * y;
        Y[(size_t)i * nrhs + j] = y;
    }
}

// transpose [R][C] fp32 -> [C][R] split into bf16 hi/lo
__global__ void trans_split(const float* __restrict__ in,
                            __nv_bfloat16* __restrict__ oh,
                            __nv_bfloat16* __restrict__ ol, int R, int C) {
    __shared__ float t[32][33];
    int c0 = blockIdx.x * 32, r0 = blockIdx.y * 32;
    int x = threadIdx.x, y = threadIdx.y;
#pragma unroll
    for (int i = 0; i < 32; i += 8)
        t[y + i][x] = in[(size_t)(r0 + y + i) * C + c0 + x];
    __syncthreads();
#pragma unroll
    for (int i = 0; i < 32; i += 8) {
        float v = t[x][y + i];
        size_t idx = (size_t)(c0 + y + i) * R + r0 + x;
        __nv_bfloat16 h = __float2bfloat16(v);
        oh[idx] = h;
        ol[idx] = __float2bfloat16(v - __bfloat162float(h));
    }
}

// split x fp32 -> bf16 hi/lo (vectorized)
__global__ void split_x_k(const float4* __restrict__ x, uint2* __restrict__ xh,
                          uint2* __restrict__ xl, int n4) {
    int i = blockIdx.x * blockDim.x + threadIdx.x;
    if (i >= n4) return;
    float4 v = x[i];
    uint32_t h0, l0, h1, l1;
    split2(v.x, v.y, h0, l0);
    split2(v.z, v.w, h1, l1);
    xh[i] = make_uint2(h0, h1);
    xl[i] = make_uint2(l0, l1);
}

// ======================= bf16x3 mma.sync GEMM =======================
// C[M,N] = sum_seg Aseg[M,K] @ Bseg[N,K]^T (+bias) (+relu/split)
// pairs: (Ah,Bh), (Ah,Bl), (Al,Bh).  CTA tile 128x128, BK=32, 3 stages.
#define GSTAGES 3
#define STG_BYTES 16384    // A 8KB + B 8KB per stage
#define GEMM_SMEM (GSTAGES * STG_BYTES)   // 48 KB exactly

// swizzled byte offset inside a 128x32 bf16 tile (64B rows, 4x16B segs)
__device__ __forceinline__ uint32_t swz(int r, int sg) {
    return (uint32_t)(r * 64 + ((sg ^ ((r >> 1) & 3)) << 4));
}

__device__ __forceinline__ void load_stage(uint32_t sbase, int buf,
    const __nv_bfloat16* A, const __nv_bfloat16* B,
    int rowB, int colB, int K, int off, int tid) {
    uint32_t sA = sbase + (uint32_t)buf * STG_BYTES;
    uint32_t sB = sA + 8192;
#pragma unroll
    for (int i = 0; i < 2; i++) {
        int flat = tid + i * 256;          // 0..511
        int r = flat >> 2, sg = flat & 3;
        uint32_t sw = swz(r, sg);
        cp16(sA + sw, A + (size_t)(rowB + r) * K + off + sg * 8);
        cp16(sB + sw, B + (size_t)(colB + r) * K + off + sg * 8);
    }
    cp_commit();
}

template <bool FUSE>   // FUSE: relu + write bf16 hi/lo (Ch,Cl); else fp32 Cf
__global__ void __launch_bounds__(256, 1) gemm_bf16x3(
    const __nv_bfloat16* __restrict__ Ah, const __nv_bfloat16* __restrict__ Al,
    const __nv_bfloat16* __restrict__ Bh, const __nv_bfloat16* __restrict__ Bl,
    const float* __restrict__ bias, float* __restrict__ Cf,
    __nv_bfloat16* __restrict__ Ch, __nv_bfloat16* __restrict__ Cl,
    int N, int K) {
    extern __shared__ char smem[];
    uint32_t sb = smem_u32(smem);
    const int tid = threadIdx.x;
    const int lane = tid & 31, wid = tid >> 5;
    const int wm = wid & 3, wn = wid >> 2;       // warp tile: 32(m) x 64(n)
    const int rowB = blockIdx.y * 128, colB = blockIdx.x * 128;
    const int per = K >> 5;                      // 32-K stages per segment
    const int total = 3 * per;

    float acc[2][8][4] = {};

    // prologue: stages 0,1 (seg 0 since per >= 16)
#pragma unroll
    for (int s = 0; s < GSTAGES - 1; s++)
        load_stage(sb, s, Ah, Bh, rowB, colB, K, s << 5, tid);

    const int lr = lane & 15, kh = lane >> 4;
    const int lg = lane >> 2, lt = lane & 3;

    for (int s = 0; s < total; s++) {
        cp_wait<GSTAGES - 2>();
        __syncthreads();

        int pf = s + GSTAGES - 1;
        if (pf < total) {
            int seg = (pf >= per) + (pf >= 2 * per);
            const __nv_bfloat16* As_ = (seg < 2) ? Ah : Al;
            const __nv_bfloat16* Bs_ = (seg == 1) ? Bl : Bh;
            int off = (pf - seg * per) << 5;
            load_stage(sb, pf % GSTAGES, As_, Bs_, rowB, colB, K, off, tid);
        } else {
            cp_commit();
        }

        uint32_t sA = sb + (uint32_t)(s % GSTAGES) * STG_BYTES;
        uint32_t sBs = sA + 8192;
#pragma unroll
        for (int kk = 0; kk < 2; kk++) {
            uint32_t a[2][4];
#pragma unroll
            for (int mt = 0; mt < 2; mt++) {
                int r = wm * 32 + mt * 16 + lr;
                ldm_x4(a[mt][0], a[mt][1], a[mt][2], a[mt][3],
                       sA + swz(r, 2 * kk + kh));
            }
#pragma unroll
            for (int pt = 0; pt < 4; pt++) {
                uint32_t b0, b1, b2, b3;
                int r = wn * 64 + pt * 16 + lr;
                ldm_x4(b0, b1, b2, b3, sBs + swz(r, 2 * kk + kh));
#pragma unroll
                for (int mt = 0; mt < 2; mt++) {
                    mma16816(acc[mt][2 * pt],     a[mt], b0, b2);
                    mma16816(acc[mt][2 * pt + 1], a[mt], b1, b3);
                }
            }
        }
        __syncthreads();
    }

    // epilogue
#pragma unroll
    for (int mt = 0; mt < 2; mt++) {
        int r0 = rowB + wm * 32 + mt * 16 + lg;
#pragma unroll
        for (int n8 = 0; n8 < 8; n8++) {
            int c = colB + wn * 64 + n8 * 8 + 2 * lt;
            float b0v = bias[c], b1v = bias[c + 1];
            float v0 = acc[mt][n8][0] + b0v;
            float v1 = acc[mt][n8][1] + b1v;
            float v2 = acc[mt][n8][2] + b0v;
            float v3 = acc[mt][n8][3] + b1v;
            if (FUSE) {
                v0 = fmaxf(v0, 0.f); v1 = fmaxf(v1, 0.f);
                v2 = fmaxf(v2, 0.f); v3 = fmaxf(v3, 0.f);
                uint32_t hi, lo;
                split2(v0, v1, hi, lo);
                *(uint32_t*)(Ch + (size_t)r0 * N + c) = hi;
                *(uint32_t*)(Cl + (size_t)r0 * N + c) = lo;
                split2(v2, v3, hi, lo);
                *(uint32_t*)(Ch + (size_t)(r0 + 8) * N + c) = hi;
                *(uint32_t*)(Cl + (size_t)(r0 + 8) * N + c) = lo;
            } else {
                *(float2*)(Cf + (size_t)r0 * N + c) = make_float2(v0, v1);
                *(float2*)(Cf + (size_t)(r0 + 8) * N + c) = make_float2(v2, v3);
            }
        }
    }
}

// ======================= launch =======================
extern "C" void kernel_launch(void* const* d_in, const int* in_sizes, int n_in,
                              void* d_out, int out_size) {
    const float* x  = (const float*)d_in[0];
    const float* d1 = (const float*)d_in[1];
    const float* l1 = (const float*)d_in[2];
    const float* u1 = (const float*)d_in[3];
    const float* W1 = (const float*)d_in[4];
    const float* b1 = (const float*)d_in[5];
    const float* d2 = (const float*)d_in[6];
    const float* l2 = (const float*)d_in[7];
    const float* u2 = (const float*)d_in[8];
    const float* W2 = (const float*)d_in[9];
    const float* b2 = (const float*)d_in[10];
    float* out = (float*)d_out;

    float *lo1, *cp1, *rd1, *lo2, *cp2, *rd2, *Y1, *Y2;
    __nv_bfloat16 *W1h, *W1l, *W2h, *W2l, *xh, *xl, *hh, *hl;
    cudaGetSymbolAddress((void**)&lo1, g_lo1);
    cudaGetSymbolAddress((void**)&cp1, g_cp1);
    cudaGetSymbolAddress((void**)&rd1, g_rd1);
    cudaGetSymbolAddress((void**)&lo2, g_lo2);
    cudaGetSymbolAddress((void**)&cp2, g_cp2);
    cudaGetSymbolAddress((void**)&rd2, g_rd2);
    cudaGetSymbolAddress((void**)&Y1,  g_Y1);
    cudaGetSymbolAddress((void**)&Y2,  g_Y2);
    cudaGetSymbolAddress((void**)&W1h, g_W1h);
    cudaGetSymbolAddress((void**)&W1l, g_W1l);
    cudaGetSymbolAddress((void**)&W2h, g_W2h);
    cudaGetSymbolAddress((void**)&W2l, g_W2l);
    cudaGetSymbolAddress((void**)&xh,  g_xh);
    cudaGetSymbolAddress((void**)&xl,  g_xl);
    cudaGetSymbolAddress((void**)&hh,  g_hh);
    cudaGetSymbolAddress((void**)&hl,  g_hl);

    // 1) factorize M1^T, M2^T
    prep_both<<<2, 256>>>(d1, l1, u1, d2, l2, u2, lo1, cp1, rd1, lo2, cp2, rd2);

    // 2) fold solves into weights: Y = solve(M^T, W^T)
    solve_rhs<<<F_HID / 128, 128>>>(lo1, cp1, rd1, W1, F_IN,  F_HID, Y1);
    solve_rhs<<<F_OUT / 128, 128>>>(lo2, cp2, rd2, W2, F_HID, F_OUT, Y2);

    // 3) transpose + bf16 hi/lo split of folded weights
    trans_split<<<dim3(F_HID / 32, F_IN / 32),  dim3(32, 8)>>>(Y1, W1h, W1l, F_IN,  F_HID);
    trans_split<<<dim3(F_OUT / 32, F_HID / 32), dim3(32, 8)>>>(Y2, W2h, W2l, F_HID, F_OUT);

    // 4) split x into bf16 hi/lo
    {
        int n4 = (N_TOK * F_IN) / 4;
        split_x_k<<<(n4 + 255) / 256, 256>>>((const float4*)x, (uint2*)xh, (uint2*)xl, n4);
    }

    // 5) h = relu(x @ W1p^T + b1), stored as bf16 hi/lo
    gemm_bf16x3<true><<<dim3(F_HID / 128, N_TOK / 128), 256, GEMM_SMEM>>>(
        xh, xl, W1h, W1l, b1, nullptr, hh, hl, F_HID, F_IN);

    // 6) out = h @ W2p^T + b2 (fp32)
    gemm_bf16x3<false><<<dim3(F_OUT / 128, N_TOK / 128), 256, GEMM_SMEM>>>(
        hh, hl, W2h, W2l, b2, out, nullptr, nullptr, F_OUT, F_HID);
}

// round 4
// speedup vs baseline: 2.2089x; 1.1540x over previous
#include <cuda_runtime.h>
#include <cuda_bf16.h>
#include <math.h>
#include <stdint.h>

#define N_TOK 32768
#define F_IN  512
#define F_HID 2048
#define F_OUT 512

// ---------------- scratch (static device globals; no runtime alloc) ----------
__device__ float g_lo1[F_IN],  g_cp1[F_IN],  g_rd1[F_IN];
__device__ float g_lo2[F_HID], g_cp2[F_HID], g_rd2[F_HID];
__device__ float g_Y1[F_IN * F_HID];                 // solve(M1^T, W1^T): [512][2048]
__device__ float g_Y2[F_HID * F_OUT];                // [2048][512]
__device__ __nv_bfloat16 g_W1h[F_HID * F_IN];        // B1 hi  [2048][512]
__device__ __nv_bfloat16 g_W1l[F_HID * F_IN];        // B1 lo
__device__ __nv_bfloat16 g_W2h[F_OUT * F_HID];       // B2 hi  [512][2048]
__device__ __nv_bfloat16 g_W2l[F_OUT * F_HID];       // B2 lo
__device__ __nv_bfloat16 g_xh[(size_t)N_TOK * F_IN]; // x hi   32 MB
__device__ __nv_bfloat16 g_xl[(size_t)N_TOK * F_IN]; // x lo
__device__ __nv_bfloat16 g_hh[(size_t)N_TOK * F_HID]; // h hi  128 MB
__device__ __nv_bfloat16 g_hl[(size_t)N_TOK * F_HID]; // h lo  128 MB

// ======================= small helpers =======================
__device__ __forceinline__ uint32_t smem_u32(const void* p) {
    uint32_t a;
    asm("{ .reg .u64 t; cvta.to.shared.u64 t, %1; cvt.u32.u64 %0, t; }"
        : "=r"(a) : "l"(p));
    return a;
}

__device__ __forceinline__ void cp16(uint32_t dst, const void* src) {
    asm volatile("cp.async.cg.shared.global [%0], [%1], 16;" :: "r"(dst), "l"(src));
}
__device__ __forceinline__ void cp_commit() {
    asm volatile("cp.async.commit_group;" ::: "memory");
}
template <int NN> __device__ __forceinline__ void cp_wait() {
    asm volatile("cp.async.wait_group %0;" :: "n"(NN) : "memory");
}

__device__ __forceinline__ void ldm_x4(uint32_t& r0, uint32_t& r1, uint32_t& r2,
                                       uint32_t& r3, uint32_t a) {
    asm volatile("ldmatrix.sync.aligned.m8n8.x4.shared.b16 {%0,%1,%2,%3}, [%4];"
        : "=r"(r0), "=r"(r1), "=r"(r2), "=r"(r3) : "r"(a));
}

__device__ __forceinline__ void mma16816(float* c, const uint32_t* a,
                                         uint32_t b0, uint32_t b1) {
    asm volatile("mma.sync.aligned.m16n8k16.row.col.f32.bf16.bf16.f32 "
        "{%0,%1,%2,%3}, {%4,%5,%6,%7}, {%8,%9}, {%0,%1,%2,%3};"
        : "+f"(c[0]), "+f"(c[1]), "+f"(c[2]), "+f"(c[3])
        : "r"(a[0]), "r"(a[1]), "r"(a[2]), "r"(a[3]), "r"(b0), "r"(b1));
}

// split fp32 pair -> packed bf16 hi pair + bf16 lo pair
__device__ __forceinline__ void split2(float a, float b, uint32_t& hi, uint32_t& lo) {
    __nv_bfloat16 ha = __float2bfloat16(a), hb = __float2bfloat16(b);
    float ra = a - __bfloat162float(ha);
    float rb = b - __bfloat162float(hb);
    __nv_bfloat16 la = __float2bfloat16(ra), lb = __float2bfloat16(rb);
    hi = ((uint32_t)__bfloat16_as_ushort(hb) << 16) | (uint32_t)__bfloat16_as_ushort(ha);
    lo = ((uint32_t)__bfloat16_as_ushort(lb) << 16) | (uint32_t)__bfloat16_as_ushort(la);
}

// ======================= prep kernels =======================
__global__ void prep_both(const float* d1, const float* l1, const float* u1,
                          const float* d2, const float* l2, const float* u2,
                          float* lo1, float* cp1, float* rd1,
                          float* lo2, float* cp2, float* rd2) {
    __shared__ float sd[2048], slo[2048], sup[2048];
    const float *d, *l, *u; float *lo, *cp, *rd; int n;
    if (blockIdx.x == 0) { d = d1; l = l1; u = u1; lo = lo1; cp = cp1; rd = rd1; n = F_IN; }
    else                 { d = d2; l = l2; u = u2; lo = lo2; cp = cp2; rd = rd2; n = F_HID; }
    int t = threadIdx.x;
    for (int i = t; i < n; i += blockDim.x) {
        float di = d[i];
        float sp = (di > 20.f) ? di : log1pf(expf(di));
        sd[i]  = sp + 2.f;
        slo[i] = (i > 0)     ? tanhf(u[i - 1]) : 0.f;   // sub of M^T
        sup[i] = (i < n - 1) ? tanhf(l[i])     : 0.f;   // super of M^T
    }
    __syncthreads();
    if (t == 0) {
        float cprev = 0.f;
        for (int i = 0; i < n; i++) {
            float den = sd[i] - slo[i] * cprev;
            float r = 1.f / den;
            sd[i] = r;
            cprev = sup[i] * r;
            sup[i] = cprev;
        }
    }
    __syncthreads();
    for (int i = t; i < n; i += blockDim.x) {
        rd[i] = sd[i]; cp[i] = sup[i]; lo[i] = slo[i];
    }
}

// Solve M^T Y = R^T. R: [nrhs][n] row-major; Y: [n][nrhs]. 1 thread / RHS.
__global__ void solve_rhs(const float* __restrict__ lo, const float* __restrict__ cp,
                          const float* __restrict__ rd, const float* __restrict__ R,
                          int n, int nrhs, float* __restrict__ Y) {
    int j = blockIdx.x * blockDim.x + threadIdx.x;
    if (j >= nrhs) return;
    const float* r = R + (size_t)j * n;
    float z = r[0] * rd[0];
    Y[j] = z;
#pragma unroll 4
    for (int i = 1; i < n; i++) {
        z = (r[i] - lo[i] * z) * rd[i];
        Y[(size_t)i * nrhs + j] = z;
    }
    float y = z;
#pragma unroll 4
    for (int i = n - 2; i >= 0; i--) {
        y = Y[(size_t)i * nrhs + j] - cp[i] * y;
        Y[(size_t)i * nrhs + j] = y;
    }
}

// transpose [R][C] fp32 -> [C][R] split into bf16 hi/lo
__global__ void trans_split(const float* __restrict__ in,
                            __nv_bfloat16* __restrict__ oh,
                            __nv_bfloat16* __restrict__ ol, int R, int C) {
    __shared__ float t[32][33];
    int c0 = blockIdx.x * 32, r0 = blockIdx.y * 32;
    int x = threadIdx.x, y = threadIdx.y;
#pragma unroll
    for (int i = 0; i < 32; i += 8)
        t[y + i][x] = in[(size_t)(r0 + y + i) * C + c0 + x];
    __syncthreads();
#pragma unroll
    for (int i = 0; i < 32; i += 8) {
        float v = t[x][y + i];
        size_t idx = (size_t)(c0 + y + i) * R + r0 + x;
        __nv_bfloat16 h = __float2bfloat16(v);
        oh[idx] = h;
        ol[idx] = __float2bfloat16(v - __bfloat162float(h));
    }
}

// split x fp32 -> bf16 hi/lo (vectorized)
__global__ void split_x_k(const float4* __restrict__ x, uint2* __restrict__ xh,
                          uint2* __restrict__ xl, int n4) {
    int i = blockIdx.x * blockDim.x + threadIdx.x;
    if (i >= n4) return;
    float4 v = x[i];
    uint32_t h0, l0, h1, l1;
    split2(v.x, v.y, h0, l0);
    split2(v.z, v.w, h1, l1);
    xh[i] = make_uint2(h0, h1);
    xl[i] = make_uint2(l0, l1);
}

// ======================= bf16x3 mma.sync GEMM (v2) =======================
// C = Ah@Bh^T + Ah@Bl^T + Al@Bh^T (+bias)(+relu/split)
// CTA 128x128, 8 warps (32x64 warp tile), BK=32.
// Each stage holds ALL FOUR tiles (Ah,Al,Bh,Bl) and issues all 3 combos.
#define GSTAGES 3
#define TILE_B  8192u                  // one 128x32 bf16 tile
#define STG_BYTES (4u * TILE_B)        // 32 KB / stage
#define GEMM_SMEM (GSTAGES * STG_BYTES) // 96 KB

// swizzled byte offset inside a 128x32 bf16 tile (64B rows, 4x16B segs)
__device__ __forceinline__ uint32_t swz(int r, int sg) {
    return (uint32_t)(r * 64 + ((sg ^ ((r >> 1) & 3)) << 4));
}

__device__ __forceinline__ void load_stage4(uint32_t sbase, int buf,
    const __nv_bfloat16* Ah, const __nv_bfloat16* Al,
    const __nv_bfloat16* Bh, const __nv_bfloat16* Bl,
    int rowB, int colB, int K, int off, int tid) {
    uint32_t s0 = sbase + (uint32_t)buf * STG_BYTES;
#pragma unroll
    for (int i = 0; i < 2; i++) {
        int flat = tid + i * 256;          // 0..511
        int r = flat >> 2, sg = flat & 3;
        uint32_t sw = swz(r, sg);
        size_t ga = (size_t)(rowB + r) * K + off + sg * 8;
        size_t gb = (size_t)(colB + r) * K + off + sg * 8;
        cp16(s0 + sw,               Ah + ga);
        cp16(s0 + TILE_B + sw,      Al + ga);
        cp16(s0 + 2 * TILE_B + sw,  Bh + gb);
        cp16(s0 + 3 * TILE_B + sw,  Bl + gb);
    }
    cp_commit();
}

template <bool FUSE>   // FUSE: relu + write bf16 hi/lo (Ch,Cl); else fp32 Cf
__global__ void __launch_bounds__(256, 2) gemm_bf16x3(
    const __nv_bfloat16* __restrict__ Ah, const __nv_bfloat16* __restrict__ Al,
    const __nv_bfloat16* __restrict__ Bh, const __nv_bfloat16* __restrict__ Bl,
    const float* __restrict__ bias, float* __restrict__ Cf,
    __nv_bfloat16* __restrict__ Ch, __nv_bfloat16* __restrict__ Cl,
    int N, int K) {
    extern __shared__ char smem[];
    uint32_t sb = smem_u32(smem);
    const int tid = threadIdx.x;
    const int lane = tid & 31, wid = tid >> 5;
    const int wm = wid & 3, wn = wid >> 2;       // warp tile: 32(m) x 64(n)
    const int rowB = blockIdx.y * 128, colB = blockIdx.x * 128;
    const int per = K >> 5;                      // number of 32-K stages

    float acc[2][8][4] = {};

    // prologue: stages 0..GSTAGES-2
#pragma unroll
    for (int s = 0; s < GSTAGES - 1; s++)
        load_stage4(sb, s, Ah, Al, Bh, Bl, rowB, colB, K, s << 5, tid);

    const int lr = lane & 15, kh = lane >> 4;
    const int lg = lane >> 2, lt = lane & 3;

    for (int s = 0; s < per; s++) {
        cp_wait<GSTAGES - 2>();
        __syncthreads();

        int pf = s + GSTAGES - 1;
        if (pf < per)
            load_stage4(sb, pf % GSTAGES, Ah, Al, Bh, Bl, rowB, colB, K, pf << 5, tid);
        else
            cp_commit();

        uint32_t sAh = sb + (uint32_t)(s % GSTAGES) * STG_BYTES;
        uint32_t sAl = sAh + TILE_B;
        uint32_t sBh = sAh + 2 * TILE_B;
        uint32_t sBl = sAh + 3 * TILE_B;
#pragma unroll
        for (int kk = 0; kk < 2; kk++) {
            uint32_t ah[2][4], al[2][4];
#pragma unroll
            for (int mt = 0; mt < 2; mt++) {
                int r = wm * 32 + mt * 16 + lr;
                uint32_t sw = swz(r, 2 * kk + kh);
                ldm_x4(ah[mt][0], ah[mt][1], ah[mt][2], ah[mt][3], sAh + sw);
                ldm_x4(al[mt][0], al[mt][1], al[mt][2], al[mt][3], sAl + sw);
            }
#pragma unroll
            for (int pt = 0; pt < 4; pt++) {
                int r = wn * 64 + pt * 16 + lr;
                uint32_t sw = swz(r, 2 * kk + kh);
                uint32_t bh0, bh1, bh2, bh3, bl0, bl1, bl2, bl3;
                ldm_x4(bh0, bh1, bh2, bh3, sBh + sw);
                ldm_x4(bl0, bl1, bl2, bl3, sBl + sw);
#pragma unroll
                for (int mt = 0; mt < 2; mt++) {
                    mma16816(acc[mt][2 * pt],     ah[mt], bh0, bh2);
                    mma16816(acc[mt][2 * pt + 1], ah[mt], bh1, bh3);
                    mma16816(acc[mt][2 * pt],     ah[mt], bl0, bl2);
                    mma16816(acc[mt][2 * pt + 1], ah[mt], bl1, bl3);
                    mma16816(acc[mt][2 * pt],     al[mt], bh0, bh2);
                    mma16816(acc[mt][2 * pt + 1], al[mt], bh1, bh3);
                }
            }
        }
        __syncthreads();
    }

    // epilogue
#pragma unroll
    for (int mt = 0; mt < 2; mt++) {
        int r0 = rowB + wm * 32 + mt * 16 + lg;
#pragma unroll
        for (int n8 = 0; n8 < 8; n8++) {
            int c = colB + wn * 64 + n8 * 8 + 2 * lt;
            float b0v = bias[c], b1v = bias[c + 1];
            float v0 = acc[mt][n8][0] + b0v;
            float v1 = acc[mt][n8][1] + b1v;
            float v2 = acc[mt][n8][2] + b0v;
            float v3 = acc[mt][n8][3] + b1v;
            if (FUSE) {
                v0 = fmaxf(v0, 0.f); v1 = fmaxf(v1, 0.f);
                v2 = fmaxf(v2, 0.f); v3 = fmaxf(v3, 0.f);
                uint32_t hi, lo;
                split2(v0, v1, hi, lo);
                *(uint32_t*)(Ch + (size_t)r0 * N + c) = hi;
                *(uint32_t*)(Cl + (size_t)r0 * N + c) = lo;
                split2(v2, v3, hi, lo);
                *(uint32_t*)(Ch + (size_t)(r0 + 8) * N + c) = hi;
                *(uint32_t*)(Cl + (size_t)(r0 + 8) * N + c) = lo;
            } else {
                *(float2*)(Cf + (size_t)r0 * N + c) = make_float2(v0, v1);
                *(float2*)(Cf + (size_t)(r0 + 8) * N + c) = make_float2(v2, v3);
            }
        }
    }
}

// ======================= launch =======================
extern "C" void kernel_launch(void* const* d_in, const int* in_sizes, int n_in,
                              void* d_out, int out_size) {
    const float* x  = (const float*)d_in[0];
    const float* d1 = (const float*)d_in[1];
    const float* l1 = (const float*)d_in[2];
    const float* u1 = (const float*)d_in[3];
    const float* W1 = (const float*)d_in[4];
    const float* b1 = (const float*)d_in[5];
    const float* d2 = (const float*)d_in[6];
    const float* l2 = (const float*)d_in[7];
    const float* u2 = (const float*)d_in[8];
    const float* W2 = (const float*)d_in[9];
    const float* b2 = (const float*)d_in[10];
    float* out = (float*)d_out;

    float *lo1, *cp1, *rd1, *lo2, *cp2, *rd2, *Y1, *Y2;
    __nv_bfloat16 *W1h, *W1l, *W2h, *W2l, *xh, *xl, *hh, *hl;
    cudaGetSymbolAddress((void**)&lo1, g_lo1);
    cudaGetSymbolAddress((void**)&cp1, g_cp1);
    cudaGetSymbolAddress((void**)&rd1, g_rd1);
    cudaGetSymbolAddress((void**)&lo2, g_lo2);
    cudaGetSymbolAddress((void**)&cp2, g_cp2);
    cudaGetSymbolAddress((void**)&rd2, g_rd2);
    cudaGetSymbolAddress((void**)&Y1,  g_Y1);
    cudaGetSymbolAddress((void**)&Y2,  g_Y2);
    cudaGetSymbolAddress((void**)&W1h, g_W1h);
    cudaGetSymbolAddress((void**)&W1l, g_W1l);
    cudaGetSymbolAddress((void**)&W2h, g_W2h);
    cudaGetSymbolAddress((void**)&W2l, g_W2l);
    cudaGetSymbolAddress((void**)&xh,  g_xh);
    cudaGetSymbolAddress((void**)&xl,  g_xl);
    cudaGetSymbolAddress((void**)&hh,  g_hh);
    cudaGetSymbolAddress((void**)&hl,  g_hl);

    // opt-in to 96KB dynamic smem (idempotent, capture-safe: not a stream op)
    cudaFuncSetAttribute(gemm_bf16x3<true>,
                         cudaFuncAttributeMaxDynamicSharedMemorySize, GEMM_SMEM);
    cudaFuncSetAttribute(gemm_bf16x3<false>,
                         cudaFuncAttributeMaxDynamicSharedMemorySize, GEMM_SMEM);

    // 1) factorize M1^T, M2^T
    prep_both<<<2, 256>>>(d1, l1, u1, d2, l2, u2, lo1, cp1, rd1, lo2, cp2, rd2);

    // 2) fold solves into weights: Y = solve(M^T, W^T)
    solve_rhs<<<F_HID / 128, 128>>>(lo1, cp1, rd1, W1, F_IN,  F_HID, Y1);
    solve_rhs<<<F_OUT / 128, 128>>>(lo2, cp2, rd2, W2, F_HID, F_OUT, Y2);

    // 3) transpose + bf16 hi/lo split of folded weights
    trans_split<<<dim3(F_HID / 32, F_IN / 32),  dim3(32, 8)>>>(Y1, W1h, W1l, F_IN,  F_HID);
    trans_split<<<dim3(F_OUT / 32, F_HID / 32), dim3(32, 8)>>>(Y2, W2h, W2l, F_HID, F_OUT);

    // 4) split x into bf16 hi/lo
    {
        int n4 = (N_TOK * F_IN) / 4;
        split_x_k<<<(n4 + 255) / 256, 256>>>((const float4*)x, (uint2*)xh, (uint2*)xl, n4);
    }

    // 5) h = relu(x @ W1p^T + b1), stored as bf16 hi/lo
    gemm_bf16x3<true><<<dim3(F_HID / 128, N_TOK / 128), 256, GEMM_SMEM>>>(
        xh, xl, W1h, W1l, b1, nullptr, hh, hl, F_HID, F_IN);

    // 6) out = h @ W2p^T + b2 (fp32)
    gemm_bf16x3<false><<<dim3(F_OUT / 128, N_TOK / 128), 256, GEMM_SMEM>>>(
        hh, hl, W2h, W2l, b2, out, nullptr, nullptr, F_OUT, F_HID);
}